// round 11
// baseline (speedup 1.0000x reference)
#include <cuda_runtime.h>
#include <cuda_bf16.h>
#include <math.h>
#include <cstdint>

#define Bb 4
#define Nn 256
#define Cc 32
#define Mm 4
#define OUTD 64

// ---------------- scratch (no allocation allowed) ----------------
__device__ float g_SJ[Bb*Nn*Cc];
__device__ float g_SI[Bb*Nn*Cc];
__device__ float g_DG[Bb*Nn*Cc];
__device__ float g_e [Bb*Nn*Mm];
__device__ float g_R [Bb*Nn*Mm*Cc];
__device__ float g_Q [Bb*Nn*Mm*Cc];
__device__ float g_C0[Bb*OUTD];
__device__ float g_Add[Bb*Nn*OUTD];
// bf16 weights, [n=256 rows][k=128]: [WA_hi(c 0-31) | WB_hi | WA_lo | WB_lo]
__device__ uint4 g_Wb4[256 * 128 * 2 / 16];

__device__ __forceinline__ uint32_t smem_u32(const void* p) {
    uint32_t a;
    asm("{ .reg .u64 t; cvta.to.shared.u64 t, %1; cvt.u32.u64 %0, t; }" : "=r"(a) : "l"(p));
    return a;
}

// ---------------- kernel 1: unweighted contractions (vectorized) ----------------
__global__ void k_contract1(const float* __restrict__ x) {
    int bn = blockIdx.x; int b = bn >> 8; int n = bn & 255;
    int t = threadIdx.x; int v = t & 7; int g = t >> 3;   // 256 threads
    const float4* xb4 = (const float4*)(x + (size_t)b * Nn * Nn * Cc);
    __shared__ float4 red[32][8];

    // row pass: sum over j of x[n, j, :]
    float4 a = make_float4(0.f, 0.f, 0.f, 0.f);
    #pragma unroll 4
    for (int j = g; j < Nn; j += 32) {
        float4 u = xb4[((size_t)n * Nn + j) * 8 + v];
        a.x += u.x; a.y += u.y; a.z += u.z; a.w += u.w;
    }
    red[g][v] = a; __syncthreads();
    if (g < 8) {
        float4 s = red[g][v];
        #pragma unroll
        for (int q = 1; q < 4; ++q) {
            float4 u = red[g + 8 * q][v];
            s.x += u.x; s.y += u.y; s.z += u.z; s.w += u.w;
        }
        red[g][v] = s;
    }
    __syncthreads();
    if (t < 8) {
        float4 s = red[0][t];
        #pragma unroll
        for (int q = 1; q < 8; ++q) {
            float4 u = red[q][t];
            s.x += u.x; s.y += u.y; s.z += u.z; s.w += u.w;
        }
        ((float4*)g_SI)[((size_t)b * Nn + n) * 8 + t] = s;
    }
    __syncthreads();

    // col pass: sum over i of x[i, n, :]
    a = make_float4(0.f, 0.f, 0.f, 0.f);
    #pragma unroll 4
    for (int i = g; i < Nn; i += 32) {
        float4 u = xb4[((size_t)i * Nn + n) * 8 + v];
        a.x += u.x; a.y += u.y; a.z += u.z; a.w += u.w;
    }
    red[g][v] = a; __syncthreads();
    if (g < 8) {
        float4 s = red[g][v];
        #pragma unroll
        for (int q = 1; q < 4; ++q) {
            float4 u = red[g + 8 * q][v];
            s.x += u.x; s.y += u.y; s.z += u.z; s.w += u.w;
        }
        red[g][v] = s;
    }
    __syncthreads();
    if (t < 8) {
        float4 s = red[0][t];
        #pragma unroll
        for (int q = 1; q < 8; ++q) {
            float4 u = red[q][t];
            s.x += u.x; s.y += u.y; s.z += u.z; s.w += u.w;
        }
        ((float4*)g_SJ)[((size_t)b * Nn + n) * 8 + t] = s;
    }
    if (t >= 8 && t < 16) {
        int v2 = t - 8;
        ((float4*)g_DG)[((size_t)b * Nn + n) * 8 + v2] = xb4[((size_t)n * Nn + n) * 8 + v2];
    }
}

// ---------------- kernel 2: neighborhood sigmoid ----------------
__global__ void k_neighbs(const float* __restrict__ w1, const float* __restrict__ b1,
                          const float* __restrict__ w0, const float* __restrict__ b0) {
    int b = blockIdx.x; int t = threadIdx.x; int c = t & 31; int g = t >> 5;
    __shared__ float red[8][32];
    __shared__ float s_rcs[32], s_ds[32], sw1[96 * 4], sw0[64 * 4], so0[4];

    for (int k = t; k < 384; k += 256) sw1[k] = w1[k];
    if (t < 256) sw0[t] = w0[t];

    float a = 0.f;
    for (int j = g; j < Nn; j += 8) a += g_SJ[(b * Nn + j) * Cc + c];
    red[g][c] = a; __syncthreads();
    if (g == 0) {
        float s = 0.f;
        #pragma unroll
        for (int q = 0; q < 8; ++q) s += red[q][c];
        s_rcs[c] = s * (1.f / ((float)Nn * (float)Nn));
    }
    __syncthreads();
    a = 0.f;
    for (int j = g; j < Nn; j += 8) a += g_DG[(b * Nn + j) * Cc + c];
    red[g][c] = a; __syncthreads();
    if (g == 0) {
        float s = 0.f;
        #pragma unroll
        for (int q = 0; q < 8; ++q) s += red[q][c];
        s_ds[c] = s * (1.f / (float)Nn);
    }
    __syncthreads();

    if (t < 4) {
        float v = b0[t];
        #pragma unroll 8
        for (int cc = 0; cc < 32; ++cc)
            v += s_rcs[cc] * sw0[cc * 4 + t] + s_ds[cc] * sw0[(32 + cc) * 4 + t];
        so0[t] = v;
    }
    __syncthreads();

    int n = t;
    float nb0 = so0[0] + b1[0], nb1 = so0[1] + b1[1];
    float nb2 = so0[2] + b1[2], nb3 = so0[3] + b1[3];
    const float invN = 1.f / (float)Nn;
    #pragma unroll 4
    for (int cc = 0; cc < 32; ++cc) {
        float rs = g_SJ[(b * Nn + n) * Cc + cc] * invN;
        float cs = g_SI[(b * Nn + n) * Cc + cc] * invN;
        float dg = g_DG[(b * Nn + n) * Cc + cc];
        nb0 += rs * sw1[cc * 4 + 0] + cs * sw1[(32 + cc) * 4 + 0] + dg * sw1[(64 + cc) * 4 + 0];
        nb1 += rs * sw1[cc * 4 + 1] + cs * sw1[(32 + cc) * 4 + 1] + dg * sw1[(64 + cc) * 4 + 1];
        nb2 += rs * sw1[cc * 4 + 2] + cs * sw1[(32 + cc) * 4 + 2] + dg * sw1[(64 + cc) * 4 + 2];
        nb3 += rs * sw1[cc * 4 + 3] + cs * sw1[(32 + cc) * 4 + 3] + dg * sw1[(64 + cc) * 4 + 3];
    }
    g_e[(b * Nn + n) * 4 + 0] = 1.f / (1.f + expf(-nb0));
    g_e[(b * Nn + n) * 4 + 1] = 1.f / (1.f + expf(-nb1));
    g_e[(b * Nn + n) * 4 + 2] = 1.f / (1.f + expf(-nb2));
    g_e[(b * Nn + n) * 4 + 3] = 1.f / (1.f + expf(-nb3));
}

// ---------------- kernel 3: e-weighted contractions (vectorized) ----------------
__global__ void k_weighted(const float* __restrict__ x) {
    int bn = blockIdx.x; int b = bn >> 8; int n = bn & 255;
    int t = threadIdx.x; int v = t & 7; int g = t >> 3;
    __shared__ float4 se4[Nn];
    __shared__ float4 red[32][4][8];
    se4[t] = ((const float4*)g_e)[b * Nn + t];
    __syncthreads();
    const float4* xb4 = (const float4*)(x + (size_t)b * Nn * Nn * Cc);

    // row pass -> Q[n,m,c] = sum_j e[j,m] x[n,j,c]
    {
        float4 q0 = make_float4(0,0,0,0), q1 = q0, q2 = q0, q3 = q0;
        #pragma unroll 4
        for (int j = g; j < Nn; j += 32) {
            float4 u = xb4[((size_t)n * Nn + j) * 8 + v];
            float4 e = se4[j];
            q0.x += e.x*u.x; q0.y += e.x*u.y; q0.z += e.x*u.z; q0.w += e.x*u.w;
            q1.x += e.y*u.x; q1.y += e.y*u.y; q1.z += e.y*u.z; q1.w += e.y*u.w;
            q2.x += e.z*u.x; q2.y += e.z*u.y; q2.z += e.z*u.z; q2.w += e.z*u.w;
            q3.x += e.w*u.x; q3.y += e.w*u.y; q3.z += e.w*u.z; q3.w += e.w*u.w;
        }
        red[g][0][v] = q0; red[g][1][v] = q1; red[g][2][v] = q2; red[g][3][v] = q3;
    }
    __syncthreads();
    if (g < 8) {
        #pragma unroll
        for (int m = 0; m < 4; ++m) {
            float4 s = red[g][m][v];
            #pragma unroll
            for (int q = 1; q < 4; ++q) {
                float4 u = red[g + 8 * q][m][v];
                s.x += u.x; s.y += u.y; s.z += u.z; s.w += u.w;
            }
            red[g][m][v] = s;
        }
    }
    __syncthreads();
    if (t < 32) {
        int m = t >> 3, vv = t & 7;
        float4 s = red[0][m][vv];
        #pragma unroll
        for (int q = 1; q < 8; ++q) {
            float4 u = red[q][m][vv];
            s.x += u.x; s.y += u.y; s.z += u.z; s.w += u.w;
        }
        ((float4*)g_Q)[(((size_t)b * Nn + n) * 4 + m) * 8 + vv] = s;
    }
    __syncthreads();

    // col pass -> R[n,m,c] = sum_i e[i,m] x[i,n,c]
    {
        float4 q0 = make_float4(0,0,0,0), q1 = q0, q2 = q0, q3 = q0;
        #pragma unroll 4
        for (int i = g; i < Nn; i += 32) {
            float4 u = xb4[((size_t)i * Nn + n) * 8 + v];
            float4 e = se4[i];
            q0.x += e.x*u.x; q0.y += e.x*u.y; q0.z += e.x*u.z; q0.w += e.x*u.w;
            q1.x += e.y*u.x; q1.y += e.y*u.y; q1.z += e.y*u.z; q1.w += e.y*u.w;
            q2.x += e.z*u.x; q2.y += e.z*u.y; q2.z += e.z*u.z; q2.w += e.z*u.w;
            q3.x += e.w*u.x; q3.y += e.w*u.y; q3.z += e.w*u.z; q3.w += e.w*u.w;
        }
        red[g][0][v] = q0; red[g][1][v] = q1; red[g][2][v] = q2; red[g][3][v] = q3;
    }
    __syncthreads();
    if (g < 8) {
        #pragma unroll
        for (int m = 0; m < 4; ++m) {
            float4 s = red[g][m][v];
            #pragma unroll
            for (int q = 1; q < 4; ++q) {
                float4 u = red[g + 8 * q][m][v];
                s.x += u.x; s.y += u.y; s.z += u.z; s.w += u.w;
            }
            red[g][m][v] = s;
        }
    }
    __syncthreads();
    if (t < 32) {
        int m = t >> 3, vv = t & 7;
        float4 s = red[0][m][vv];
        #pragma unroll
        for (int q = 1; q < 8; ++q) {
            float4 u = red[q][m][vv];
            s.x += u.x; s.y += u.y; s.z += u.z; s.w += u.w;
        }
        ((float4*)g_R)[(((size_t)b * Nn + n) * 4 + m) * 8 + vv] = s;
    }
}

// ---------------- kernel 4a: 0d term, parallelized ----------------
__global__ void k_c0(const float* __restrict__ w0d, const float* __restrict__ b0d,
                     const float* __restrict__ b2d) {
    int b = blockIdx.x, t = threadIdx.x; // 1024 threads
    __shared__ float redA[8][128], redD[8][128];
    __shared__ float obj0[256];
    __shared__ float redM[8][64];
    {
        int g = t >> 7, mc = t & 127, m = mc >> 5, c = mc & 31;
        float a = 0.f, d = 0.f;
        #pragma unroll 4
        for (int j = g; j < Nn; j += 8) {
            float ev = g_e[(b * Nn + j) * 4 + m];
            a += ev * g_R[((b * Nn + j) * 4 + m) * 32 + c];
            d += ev * ev * g_DG[(b * Nn + j) * Cc + c];
        }
        redA[g][mc] = a; redD[g][mc] = d;
    }
    __syncthreads();
    if (t < 128) {
        float sa = 0.f, sd = 0.f;
        #pragma unroll
        for (int q = 0; q < 8; ++q) { sa += redA[q][t]; sd += redD[q][t]; }
        obj0[t]       = sa * (1.f / ((float)Nn * (float)Nn));
        obj0[128 + t] = sd * (1.f / (float)Nn);
    }
    __syncthreads();
    if (t < 512) {
        int o = t & 63, q = t >> 6;
        float s = 0.f;
        #pragma unroll 4
        for (int k = q; k < 256; k += 8) s += obj0[k] * w0d[k * 64 + o];
        redM[q][o] = s;
    }
    __syncthreads();
    if (t < 64) {
        float s = b0d[t] + b2d[t];
        #pragma unroll
        for (int q = 0; q < 8; ++q) s += redM[q][t];
        g_C0[b * 64 + t] = s;
    }
}

// ---------------- kernel 4b: per-(b,j) additive term ----------------
__global__ void k_add(const float* __restrict__ w1d, const float* __restrict__ b1d) {
    int bn = blockIdx.x; int b = bn >> 8; int n = bn & 255;
    int t = threadIdx.x; // 128 threads
    __shared__ float obj1[384];
    {
        int m = t >> 5, c = t & 31;
        float ev = g_e[(b * Nn + n) * 4 + m];
        const float invN = 1.f / (float)Nn;
        obj1[t]       = ev * g_R[((b * Nn + n) * 4 + m) * 32 + c] * invN;
        obj1[128 + t] = ev * g_Q[((b * Nn + n) * 4 + m) * 32 + c] * invN;
        obj1[256 + t] = ev * ev * g_DG[(b * Nn + n) * Cc + c];
    }
    __syncthreads();
    if (t < 64) {
        float a = b1d[t] + g_C0[b * 64 + t];
        #pragma unroll 8
        for (int k = 0; k < 384; ++k) a += obj1[k] * w1d[k * 64 + t];
        g_Add[(b * Nn + n) * 64 + t] = a;
    }
}

// ---------------- kernel W-prep ----------------
__global__ void k_wprep(const float* __restrict__ w2d) {
    int idx = blockIdx.x * 256 + threadIdx.x; // 8192 = 256 n * 32 c
    if (idx >= 8192) return;
    int n = idx >> 5, c = idx & 31;
    int m = n >> 6, o = n & 63;
    float vA = w2d[(m * 32 + c) * 64 + o];
    float vB = w2d[(128 + m * 32 + c) * 64 + o];
    __nv_bfloat16 hA = __float2bfloat16_rn(vA);
    __nv_bfloat16 lA = __float2bfloat16_rn(vA - __bfloat162float(hA));
    __nv_bfloat16 hB = __float2bfloat16_rn(vB);
    __nv_bfloat16 lB = __float2bfloat16_rn(vB - __bfloat162float(hB));
    __nv_bfloat16* W = (__nv_bfloat16*)g_Wb4;
    W[n * 128 + c]      = hA;
    W[n * 128 + 32 + c] = hB;
    W[n * 128 + 64 + c] = lA;
    W[n * 128 + 96 + c] = lB;
}

// ---------------- main mma.sync kernel (ldmatrix mainloop) ----------------
#define RSA 136
#define RSB 136
#define RSR 68
#define OFF_A 0
#define OFF_B 34816
#define OFF_R0 104448
#define OFF_R1 139264
#define OFF_SEJ 174080
#define SM_BYTES 176128

__device__ __forceinline__ void mma_bf16(float* c, uint32_t a0, uint32_t a1,
                                         uint32_t a2, uint32_t a3,
                                         uint32_t b0, uint32_t b1) {
    asm volatile(
        "mma.sync.aligned.m16n8k16.row.col.f32.bf16.bf16.f32 "
        "{%0,%1,%2,%3}, {%4,%5,%6,%7}, {%8,%9}, {%0,%1,%2,%3};"
        : "+f"(c[0]), "+f"(c[1]), "+f"(c[2]), "+f"(c[3])
        : "r"(a0), "r"(a1), "r"(a2), "r"(a3), "r"(b0), "r"(b1));
}
__device__ __forceinline__ void ldsm4(uint32_t& r0, uint32_t& r1, uint32_t& r2,
                                      uint32_t& r3, uint32_t addr) {
    asm volatile("ldmatrix.sync.aligned.m8n8.x4.shared.b16 {%0,%1,%2,%3}, [%4];"
        : "=r"(r0), "=r"(r1), "=r"(r2), "=r"(r3) : "r"(addr));
}

__global__ __launch_bounds__(512, 1)
void k_main_mma(const float* __restrict__ x, float* __restrict__ out) {
    const int b = blockIdx.z;
    const int i = blockIdx.y;
    const int J = blockIdx.x * 128;
    const int tid = threadIdx.x;
    const int w = tid >> 5, lane = tid & 31;
    const int g = lane >> 2, tig = lane & 3;
    const int mrow = w & 7, ngrp = w >> 3;

    extern __shared__ char sm[];
    __nv_bfloat16* Asm = (__nv_bfloat16*)(sm + OFF_A);
    __nv_bfloat16* Bsm = (__nv_bfloat16*)(sm + OFF_B);
    float* R0  = (float*)(sm + OFF_R0);
    float* R1  = (float*)(sm + OFF_R1);
    float* sej = (float*)(sm + OFF_SEJ);

    // ---- stage B: global bf16 -> smem with row padding 128->136 ----
    {
        const uint4* src = g_Wb4;
        #pragma unroll
        for (int it = 0; it < 8; ++it) {
            int lin = it * 512 + tid;            // 4096 uint4
            int row = lin >> 4, seg = lin & 15;
            *(uint4*)&Bsm[row * RSB + seg * 8] = src[lin];
        }
    }

    // ---- stage A: Xij contiguous (float4), split to bf16 hi/lo ----
    {
        const float4* xij4 = (const float4*)(x + (((size_t)b * Nn + i) * Nn + J) * Cc);
        #pragma unroll
        for (int it = 0; it < 2; ++it) {
            int q = it * 512 + tid;              // 1024 float4
            int r = q >> 3, c0 = (q & 7) * 4;
            float4 v = xij4[q];
            float vv[4] = {v.x, v.y, v.z, v.w};
            #pragma unroll
            for (int p = 0; p < 2; ++p) {
                __nv_bfloat16 h0 = __float2bfloat16_rn(vv[2*p]);
                __nv_bfloat16 h1 = __float2bfloat16_rn(vv[2*p+1]);
                __nv_bfloat16 l0 = __float2bfloat16_rn(vv[2*p] - __bfloat162float(h0));
                __nv_bfloat16 l1 = __float2bfloat16_rn(vv[2*p+1] - __bfloat162float(h1));
                *(__nv_bfloat162*)&Asm[r * RSA + c0 + 2*p]      = __halves2bfloat162(h0, h1);
                *(__nv_bfloat162*)&Asm[r * RSA + 64 + c0 + 2*p] = __halves2bfloat162(l0, l1);
            }
        }
    }
    // ---- stage A: Xji rows (warp per row) ----
    {
        #pragma unroll
        for (int rr = w; rr < 128; rr += 16) {
            float v = x[(((size_t)b * Nn + (J + rr)) * Nn + i) * Cc + lane];
            __nv_bfloat16 h = __float2bfloat16_rn(v);
            __nv_bfloat16 l = __float2bfloat16_rn(v - __bfloat162float(h));
            Asm[rr * RSA + 32 + lane] = h;
            Asm[rr * RSA + 96 + lane] = l;
        }
    }
    // ---- stage sej ----
    {
        int r = tid >> 2, m = tid & 3;
        sej[tid] = g_e[((size_t)b * Nn + i) * 4 + m] * g_e[((size_t)b * Nn + J + r) * 4 + m];
    }
    __syncthreads();

    // ---- MMA mainloop (ldmatrix) ----
    float acc[16][4];
    #pragma unroll
    for (int u = 0; u < 16; ++u) {
        acc[u][0] = 0.f; acc[u][1] = 0.f; acc[u][2] = 0.f; acc[u][3] = 0.f;
    }

    const int arow0 = mrow * 16 + g;
    // A LDSM address: row = mrow*16 + (lane&15), k byte-off = (kk + (lane>>4)*8)*2
    const uint32_t aBase = smem_u32(Asm)
        + (uint32_t)(((mrow * 16 + (lane & 15)) * RSA + (lane >> 4) * 8) * 2);
    // B LDSM address: row = ngrp*128 + p*16 + ((lane>>3)&1)*8 + (lane&7)
    const uint32_t bBase = smem_u32(Bsm)
        + (uint32_t)(((ngrp * 128 + ((lane >> 3) & 1) * 8 + (lane & 7)) * RSB
                      + (lane >> 4) * 8) * 2);

    #pragma unroll
    for (int kki = 0; kki < 4; ++kki) {
        const int kk = kki * 16;
        uint32_t ah0, ah1, ah2, ah3, al0, al1, al2, al3;
        ldsm4(ah0, ah1, ah2, ah3, aBase + kk * 2);
        ldsm4(al0, al1, al2, al3, aBase + (kk + 64) * 2);
        #pragma unroll
        for (int p = 0; p < 8; ++p) {
            uint32_t bh0, bh1, bh2, bh3, bl0, bl1, bl2, bl3;
            const uint32_t bb = bBase + (uint32_t)((p * 16 * RSB + kk) * 2);
            ldsm4(bh0, bh1, bh2, bh3, bb);
            ldsm4(bl0, bl1, bl2, bl3, bb + 128);   // +64 elements
            float* c0 = acc[2 * p];
            float* c1 = acc[2 * p + 1];
            mma_bf16(c0, ah0, ah1, ah2, ah3, bh0, bh2);
            mma_bf16(c1, ah0, ah1, ah2, ah3, bh1, bh3);
            mma_bf16(c0, al0, al1, al2, al3, bh0, bh2);
            mma_bf16(c1, al0, al1, al2, al3, bh1, bh3);
            mma_bf16(c0, ah0, ah1, ah2, ah3, bl0, bl2);
            mma_bf16(c1, ah0, ah1, ah2, ah3, bl1, bl3);
        }
    }

    // ---- epilogue: contract over m into R[point][o] ----
    {
        float* Rb = (ngrp == 0) ? R0 : R1;
        int m0 = ngrp * 2, m1 = m0 + 1;
        int r0 = arow0, r1 = arow0 + 8;
        float s00 = sej[r0 * 4 + m0], s01 = sej[r0 * 4 + m1];
        float s10 = sej[r1 * 4 + m0], s11 = sej[r1 * 4 + m1];
        #pragma unroll
        for (int oct = 0; oct < 8; ++oct) {
            int o = oct * 8 + tig * 2;
            float2 v0, v1;
            v0.x = s00 * acc[oct][0] + s01 * acc[oct + 8][0];
            v0.y = s00 * acc[oct][1] + s01 * acc[oct + 8][1];
            v1.x = s10 * acc[oct][2] + s11 * acc[oct + 8][2];
            v1.y = s10 * acc[oct][3] + s11 * acc[oct + 8][3];
            *(float2*)&Rb[r0 * RSR + o] = v0;
            *(float2*)&Rb[r1 * RSR + o] = v1;
        }
    }
    __syncthreads();

    // ---- final merge: out = R0 + R1 + Add ----
    {
        const float4* add4 = (const float4*)(g_Add + ((size_t)b * Nn + J) * 64);
        float4* out4 = (float4*)(out + (((size_t)b * Nn + i) * Nn + J) * 64);
        #pragma unroll
        for (int it = 0; it < 4; ++it) {
            int lin = it * 512 + tid;           // 2048 float4
            int r = lin >> 4, o4 = (lin & 15) * 4;
            float4 a = add4[r * 16 + (lin & 15)];
            float4 p = *(const float4*)&R0[r * RSR + o4];
            float4 q = *(const float4*)&R1[r * RSR + o4];
            float4 v;
            v.x = a.x + p.x + q.x; v.y = a.y + p.y + q.y;
            v.z = a.z + p.z + q.z; v.w = a.w + p.w + q.w;
            out4[lin] = v;
        }
    }
}

// ---------------- launcher ----------------
extern "C" void kernel_launch(void* const* d_in, const int* in_sizes, int n_in,
                              void* d_out, int out_size) {
    const float* x     = (const float*)d_in[0];
    const float* w1_nb = (const float*)d_in[1];
    const float* b1_nb = (const float*)d_in[2];
    const float* w0_nb = (const float*)d_in[3];
    const float* b0_nb = (const float*)d_in[4];
    const float* w2d   = (const float*)d_in[5];
    const float* b2d   = (const float*)d_in[6];
    const float* w1d   = (const float*)d_in[7];
    const float* b1d   = (const float*)d_in[8];
    const float* w0d   = (const float*)d_in[9];
    const float* b0d   = (const float*)d_in[10];
    float* out = (float*)d_out;

    k_wprep<<<32, 256>>>(w2d);
    k_contract1<<<Bb * Nn, 256>>>(x);
    k_neighbs<<<Bb, 256>>>(w1_nb, b1_nb, w0_nb, b0_nb);
    k_weighted<<<Bb * Nn, 256>>>(x);
    k_c0<<<Bb, 1024>>>(w0d, b0d, b2d);
    k_add<<<Bb * Nn, 128>>>(w1d, b1d);

    cudaFuncSetAttribute(k_main_mma, cudaFuncAttributeMaxDynamicSharedMemorySize, SM_BYTES);
    dim3 grid(Nn / 128, Nn, Bb);
    k_main_mma<<<grid, 512, SM_BYTES>>>(x, out);
}

// round 12
// speedup vs baseline: 1.0976x; 1.0976x over previous
#include <cuda_runtime.h>
#include <cuda_bf16.h>
#include <math.h>
#include <cstdint>

#define Bb 4
#define Nn 256
#define Cc 32
#define Mm 4
#define OUTD 64

// ---------------- scratch (no allocation allowed) ----------------
__device__ float g_SJ[Bb*Nn*Cc];
__device__ float g_SI[Bb*Nn*Cc];
__device__ float g_DG[Bb*Nn*Cc];
__device__ float g_e [Bb*Nn*Mm];
__device__ float g_R [Bb*Nn*Mm*Cc];
__device__ float g_Q [Bb*Nn*Mm*Cc];
__device__ float g_C0[Bb*OUTD];
__device__ float g_Add[Bb*Nn*OUTD];
// bf16 weights, [n=256 rows][k=128]: [WA_hi(c 0-31) | WB_hi | WA_lo | WB_lo]
__device__ uint4 g_Wb4[256 * 128 * 2 / 16];

__device__ __forceinline__ uint32_t smem_u32(const void* p) {
    uint32_t a;
    asm("{ .reg .u64 t; cvta.to.shared.u64 t, %1; cvt.u32.u64 %0, t; }" : "=r"(a) : "l"(p));
    return a;
}

// ---------------- kernel 1: unweighted contractions (vectorized) ----------------
__global__ void k_contract1(const float* __restrict__ x) {
    int bn = blockIdx.x; int b = bn >> 8; int n = bn & 255;
    int t = threadIdx.x; int v = t & 7; int g = t >> 3;   // 256 threads
    const float4* xb4 = (const float4*)(x + (size_t)b * Nn * Nn * Cc);
    __shared__ float4 red[32][8];

    float4 a = make_float4(0.f, 0.f, 0.f, 0.f);
    #pragma unroll 4
    for (int j = g; j < Nn; j += 32) {
        float4 u = xb4[((size_t)n * Nn + j) * 8 + v];
        a.x += u.x; a.y += u.y; a.z += u.z; a.w += u.w;
    }
    red[g][v] = a; __syncthreads();
    if (g < 8) {
        float4 s = red[g][v];
        #pragma unroll
        for (int q = 1; q < 4; ++q) {
            float4 u = red[g + 8 * q][v];
            s.x += u.x; s.y += u.y; s.z += u.z; s.w += u.w;
        }
        red[g][v] = s;
    }
    __syncthreads();
    if (t < 8) {
        float4 s = red[0][t];
        #pragma unroll
        for (int q = 1; q < 8; ++q) {
            float4 u = red[q][t];
            s.x += u.x; s.y += u.y; s.z += u.z; s.w += u.w;
        }
        ((float4*)g_SI)[((size_t)b * Nn + n) * 8 + t] = s;
    }
    __syncthreads();

    a = make_float4(0.f, 0.f, 0.f, 0.f);
    #pragma unroll 4
    for (int i = g; i < Nn; i += 32) {
        float4 u = xb4[((size_t)i * Nn + n) * 8 + v];
        a.x += u.x; a.y += u.y; a.z += u.z; a.w += u.w;
    }
    red[g][v] = a; __syncthreads();
    if (g < 8) {
        float4 s = red[g][v];
        #pragma unroll
        for (int q = 1; q < 4; ++q) {
            float4 u = red[g + 8 * q][v];
            s.x += u.x; s.y += u.y; s.z += u.z; s.w += u.w;
        }
        red[g][v] = s;
    }
    __syncthreads();
    if (t < 8) {
        float4 s = red[0][t];
        #pragma unroll
        for (int q = 1; q < 8; ++q) {
            float4 u = red[q][t];
            s.x += u.x; s.y += u.y; s.z += u.z; s.w += u.w;
        }
        ((float4*)g_SJ)[((size_t)b * Nn + n) * 8 + t] = s;
    }
    if (t >= 8 && t < 16) {
        int v2 = t - 8;
        ((float4*)g_DG)[((size_t)b * Nn + n) * 8 + v2] = xb4[((size_t)n * Nn + n) * 8 + v2];
    }
}

// ---------------- kernel 2: neighborhood sigmoid ----------------
__global__ void k_neighbs(const float* __restrict__ w1, const float* __restrict__ b1,
                          const float* __restrict__ w0, const float* __restrict__ b0) {
    int b = blockIdx.x; int t = threadIdx.x; int c = t & 31; int g = t >> 5;
    __shared__ float red[8][32];
    __shared__ float s_rcs[32], s_ds[32], sw1[96 * 4], sw0[64 * 4], so0[4];

    for (int k = t; k < 384; k += 256) sw1[k] = w1[k];
    if (t < 256) sw0[t] = w0[t];

    float a = 0.f;
    for (int j = g; j < Nn; j += 8) a += g_SJ[(b * Nn + j) * Cc + c];
    red[g][c] = a; __syncthreads();
    if (g == 0) {
        float s = 0.f;
        #pragma unroll
        for (int q = 0; q < 8; ++q) s += red[q][c];
        s_rcs[c] = s * (1.f / ((float)Nn * (float)Nn));
    }
    __syncthreads();
    a = 0.f;
    for (int j = g; j < Nn; j += 8) a += g_DG[(b * Nn + j) * Cc + c];
    red[g][c] = a; __syncthreads();
    if (g == 0) {
        float s = 0.f;
        #pragma unroll
        for (int q = 0; q < 8; ++q) s += red[q][c];
        s_ds[c] = s * (1.f / (float)Nn);
    }
    __syncthreads();

    if (t < 4) {
        float v = b0[t];
        #pragma unroll 8
        for (int cc = 0; cc < 32; ++cc)
            v += s_rcs[cc] * sw0[cc * 4 + t] + s_ds[cc] * sw0[(32 + cc) * 4 + t];
        so0[t] = v;
    }
    __syncthreads();

    int n = t;
    float nb0 = so0[0] + b1[0], nb1 = so0[1] + b1[1];
    float nb2 = so0[2] + b1[2], nb3 = so0[3] + b1[3];
    const float invN = 1.f / (float)Nn;
    #pragma unroll 4
    for (int cc = 0; cc < 32; ++cc) {
        float rs = g_SJ[(b * Nn + n) * Cc + cc] * invN;
        float cs = g_SI[(b * Nn + n) * Cc + cc] * invN;
        float dg = g_DG[(b * Nn + n) * Cc + cc];
        nb0 += rs * sw1[cc * 4 + 0] + cs * sw1[(32 + cc) * 4 + 0] + dg * sw1[(64 + cc) * 4 + 0];
        nb1 += rs * sw1[cc * 4 + 1] + cs * sw1[(32 + cc) * 4 + 1] + dg * sw1[(64 + cc) * 4 + 1];
        nb2 += rs * sw1[cc * 4 + 2] + cs * sw1[(32 + cc) * 4 + 2] + dg * sw1[(64 + cc) * 4 + 2];
        nb3 += rs * sw1[cc * 4 + 3] + cs * sw1[(32 + cc) * 4 + 3] + dg * sw1[(64 + cc) * 4 + 3];
    }
    g_e[(b * Nn + n) * 4 + 0] = 1.f / (1.f + expf(-nb0));
    g_e[(b * Nn + n) * 4 + 1] = 1.f / (1.f + expf(-nb1));
    g_e[(b * Nn + n) * 4 + 2] = 1.f / (1.f + expf(-nb2));
    g_e[(b * Nn + n) * 4 + 3] = 1.f / (1.f + expf(-nb3));
}

// ---------------- kernel 3: e-weighted contractions (vectorized) ----------------
__global__ void k_weighted(const float* __restrict__ x) {
    int bn = blockIdx.x; int b = bn >> 8; int n = bn & 255;
    int t = threadIdx.x; int v = t & 7; int g = t >> 3;
    __shared__ float4 se4[Nn];
    __shared__ float4 red[32][4][8];
    se4[t] = ((const float4*)g_e)[b * Nn + t];
    __syncthreads();
    const float4* xb4 = (const float4*)(x + (size_t)b * Nn * Nn * Cc);

    {
        float4 q0 = make_float4(0,0,0,0), q1 = q0, q2 = q0, q3 = q0;
        #pragma unroll 4
        for (int j = g; j < Nn; j += 32) {
            float4 u = xb4[((size_t)n * Nn + j) * 8 + v];
            float4 e = se4[j];
            q0.x += e.x*u.x; q0.y += e.x*u.y; q0.z += e.x*u.z; q0.w += e.x*u.w;
            q1.x += e.y*u.x; q1.y += e.y*u.y; q1.z += e.y*u.z; q1.w += e.y*u.w;
            q2.x += e.z*u.x; q2.y += e.z*u.y; q2.z += e.z*u.z; q2.w += e.z*u.w;
            q3.x += e.w*u.x; q3.y += e.w*u.y; q3.z += e.w*u.z; q3.w += e.w*u.w;
        }
        red[g][0][v] = q0; red[g][1][v] = q1; red[g][2][v] = q2; red[g][3][v] = q3;
    }
    __syncthreads();
    if (g < 8) {
        #pragma unroll
        for (int m = 0; m < 4; ++m) {
            float4 s = red[g][m][v];
            #pragma unroll
            for (int q = 1; q < 4; ++q) {
                float4 u = red[g + 8 * q][m][v];
                s.x += u.x; s.y += u.y; s.z += u.z; s.w += u.w;
            }
            red[g][m][v] = s;
        }
    }
    __syncthreads();
    if (t < 32) {
        int m = t >> 3, vv = t & 7;
        float4 s = red[0][m][vv];
        #pragma unroll
        for (int q = 1; q < 8; ++q) {
            float4 u = red[q][m][vv];
            s.x += u.x; s.y += u.y; s.z += u.z; s.w += u.w;
        }
        ((float4*)g_Q)[(((size_t)b * Nn + n) * 4 + m) * 8 + vv] = s;
    }
    __syncthreads();

    {
        float4 q0 = make_float4(0,0,0,0), q1 = q0, q2 = q0, q3 = q0;
        #pragma unroll 4
        for (int i = g; i < Nn; i += 32) {
            float4 u = xb4[((size_t)i * Nn + n) * 8 + v];
            float4 e = se4[i];
            q0.x += e.x*u.x; q0.y += e.x*u.y; q0.z += e.x*u.z; q0.w += e.x*u.w;
            q1.x += e.y*u.x; q1.y += e.y*u.y; q1.z += e.y*u.z; q1.w += e.y*u.w;
            q2.x += e.z*u.x; q2.y += e.z*u.y; q2.z += e.z*u.z; q2.w += e.z*u.w;
            q3.x += e.w*u.x; q3.y += e.w*u.y; q3.z += e.w*u.z; q3.w += e.w*u.w;
        }
        red[g][0][v] = q0; red[g][1][v] = q1; red[g][2][v] = q2; red[g][3][v] = q3;
    }
    __syncthreads();
    if (g < 8) {
        #pragma unroll
        for (int m = 0; m < 4; ++m) {
            float4 s = red[g][m][v];
            #pragma unroll
            for (int q = 1; q < 4; ++q) {
                float4 u = red[g + 8 * q][m][v];
                s.x += u.x; s.y += u.y; s.z += u.z; s.w += u.w;
            }
            red[g][m][v] = s;
        }
    }
    __syncthreads();
    if (t < 32) {
        int m = t >> 3, vv = t & 7;
        float4 s = red[0][m][vv];
        #pragma unroll
        for (int q = 1; q < 8; ++q) {
            float4 u = red[q][m][vv];
            s.x += u.x; s.y += u.y; s.z += u.z; s.w += u.w;
        }
        ((float4*)g_R)[(((size_t)b * Nn + n) * 4 + m) * 8 + vv] = s;
    }
}

// ---------------- kernel 4a: 0d term ----------------
__global__ void k_c0(const float* __restrict__ w0d, const float* __restrict__ b0d,
                     const float* __restrict__ b2d) {
    int b = blockIdx.x, t = threadIdx.x; // 1024 threads
    __shared__ float redA[8][128], redD[8][128];
    __shared__ float obj0[256];
    __shared__ float redM[8][64];
    {
        int g = t >> 7, mc = t & 127, m = mc >> 5, c = mc & 31;
        float a = 0.f, d = 0.f;
        #pragma unroll 4
        for (int j = g; j < Nn; j += 8) {
            float ev = g_e[(b * Nn + j) * 4 + m];
            a += ev * g_R[((b * Nn + j) * 4 + m) * 32 + c];
            d += ev * ev * g_DG[(b * Nn + j) * Cc + c];
        }
        redA[g][mc] = a; redD[g][mc] = d;
    }
    __syncthreads();
    if (t < 128) {
        float sa = 0.f, sd = 0.f;
        #pragma unroll
        for (int q = 0; q < 8; ++q) { sa += redA[q][t]; sd += redD[q][t]; }
        obj0[t]       = sa * (1.f / ((float)Nn * (float)Nn));
        obj0[128 + t] = sd * (1.f / (float)Nn);
    }
    __syncthreads();
    if (t < 512) {
        int o = t & 63, q = t >> 6;
        float s = 0.f;
        #pragma unroll 4
        for (int k = q; k < 256; k += 8) s += obj0[k] * w0d[k * 64 + o];
        redM[q][o] = s;
    }
    __syncthreads();
    if (t < 64) {
        float s = b0d[t] + b2d[t];
        #pragma unroll
        for (int q = 0; q < 8; ++q) s += redM[q][t];
        g_C0[b * 64 + t] = s;
    }
}

// ---------------- kernel 4b: per-(b,j) additive term ----------------
__global__ void k_add(const float* __restrict__ w1d, const float* __restrict__ b1d) {
    int bn = blockIdx.x; int b = bn >> 8; int n = bn & 255;
    int t = threadIdx.x; // 128 threads
    __shared__ float obj1[384];
    {
        int m = t >> 5, c = t & 31;
        float ev = g_e[(b * Nn + n) * 4 + m];
        const float invN = 1.f / (float)Nn;
        obj1[t]       = ev * g_R[((b * Nn + n) * 4 + m) * 32 + c] * invN;
        obj1[128 + t] = ev * g_Q[((b * Nn + n) * 4 + m) * 32 + c] * invN;
        obj1[256 + t] = ev * ev * g_DG[(b * Nn + n) * Cc + c];
    }
    __syncthreads();
    if (t < 64) {
        float a = b1d[t] + g_C0[b * 64 + t];
        #pragma unroll 8
        for (int k = 0; k < 384; ++k) a += obj1[k] * w1d[k * 64 + t];
        g_Add[(b * Nn + n) * 64 + t] = a;
    }
}

// ---------------- kernel W-prep ----------------
__global__ void k_wprep(const float* __restrict__ w2d) {
    int idx = blockIdx.x * 256 + threadIdx.x; // 8192 = 256 n * 32 c
    if (idx >= 8192) return;
    int n = idx >> 5, c = idx & 31;
    int m = n >> 6, o = n & 63;
    float vA = w2d[(m * 32 + c) * 64 + o];
    float vB = w2d[(128 + m * 32 + c) * 64 + o];
    __nv_bfloat16 hA = __float2bfloat16_rn(vA);
    __nv_bfloat16 lA = __float2bfloat16_rn(vA - __bfloat162float(hA));
    __nv_bfloat16 hB = __float2bfloat16_rn(vB);
    __nv_bfloat16 lB = __float2bfloat16_rn(vB - __bfloat162float(hB));
    __nv_bfloat16* W = (__nv_bfloat16*)g_Wb4;
    W[n * 128 + c]      = hA;
    W[n * 128 + 32 + c] = hB;
    W[n * 128 + 64 + c] = lA;
    W[n * 128 + 96 + c] = lB;
}

// ---------------- persistent main mma.sync kernel ----------------
#define RSA 136
#define RSB 136
#define RSR 68
#define OFF_W  0
#define OFF_A0 69632
#define OFF_A1 104448
#define OFF_R0 139264
#define OFF_R1 174080
#define SM_BYTES 208896
#define GRID_P 152
#define NITEMS 2048

__device__ __forceinline__ void mma_bf16(float* c, uint32_t a0, uint32_t a1,
                                         uint32_t a2, uint32_t a3,
                                         uint32_t b0, uint32_t b1) {
    asm volatile(
        "mma.sync.aligned.m16n8k16.row.col.f32.bf16.bf16.f32 "
        "{%0,%1,%2,%3}, {%4,%5,%6,%7}, {%8,%9}, {%0,%1,%2,%3};"
        : "+f"(c[0]), "+f"(c[1]), "+f"(c[2]), "+f"(c[3])
        : "r"(a0), "r"(a1), "r"(a2), "r"(a3), "r"(b0), "r"(b1));
}
__device__ __forceinline__ void ldsm4(uint32_t& r0, uint32_t& r1, uint32_t& r2,
                                      uint32_t& r3, uint32_t addr) {
    asm volatile("ldmatrix.sync.aligned.m8n8.x4.shared.b16 {%0,%1,%2,%3}, [%4];"
        : "=r"(r0), "=r"(r1), "=r"(r2), "=r"(r3) : "r"(addr));
}

// store one float4 of x into A tile as hi/lo bf16 pair (Xij region)
__device__ __forceinline__ void sts_split_xij(__nv_bfloat16* Asm, int r, int c0, float4 v) {
    float vv[4] = {v.x, v.y, v.z, v.w};
    #pragma unroll
    for (int p = 0; p < 2; ++p) {
        __nv_bfloat16 h0 = __float2bfloat16_rn(vv[2*p]);
        __nv_bfloat16 h1 = __float2bfloat16_rn(vv[2*p+1]);
        __nv_bfloat16 l0 = __float2bfloat16_rn(vv[2*p] - __bfloat162float(h0));
        __nv_bfloat16 l1 = __float2bfloat16_rn(vv[2*p+1] - __bfloat162float(h1));
        *(__nv_bfloat162*)&Asm[r * RSA + c0 + 2*p]      = __halves2bfloat162(h0, h1);
        *(__nv_bfloat162*)&Asm[r * RSA + 64 + c0 + 2*p] = __halves2bfloat162(l0, l1);
    }
}

__global__ __launch_bounds__(512, 1)
void k_main_p(const float* __restrict__ x, float* __restrict__ out) {
    const int tid = threadIdx.x;
    const int w = tid >> 5, lane = tid & 31;
    const int g = lane >> 2, tig = lane & 3;
    const int mrow = w & 7, ngrp = w >> 3;

    extern __shared__ char sm[];
    __nv_bfloat16* Wsm = (__nv_bfloat16*)(sm + OFF_W);
    __nv_bfloat16* A0  = (__nv_bfloat16*)(sm + OFF_A0);
    __nv_bfloat16* A1  = (__nv_bfloat16*)(sm + OFF_A1);
    float* Rbuf[2] = { (float*)(sm + OFF_R0), (float*)(sm + OFF_R1) };

    // ---- stage W once ----
    {
        const uint4* src = g_Wb4;
        #pragma unroll
        for (int it = 0; it < 8; ++it) {
            int lin = it * 512 + tid;            // 4096 uint4
            int row = lin >> 4, seg = lin & 15;
            *(uint4*)&Wsm[row * RSB + seg * 8] = src[lin];
        }
    }

    // decode helpers
    const int r_ij = tid >> 3, c_ij = (tid & 7) * 4;       // xij vec0: row, col base
    const int r_ij2 = (tid + 512) >> 3, c_ij2 = ((tid + 512) & 7) * 4;

    // ---- prologue: stage A buffer 0 with first item ----
    {
        int L = blockIdx.x;
        int i = L & 255, b = (L >> 8) & 3, J = (L >> 10) * 128;
        const float4* xij4 = (const float4*)(x + (((size_t)b * Nn + i) * Nn + J) * Cc);
        sts_split_xij(A0, r_ij, c_ij, xij4[tid]);
        sts_split_xij(A0, r_ij2, c_ij2, xij4[tid + 512]);
        #pragma unroll
        for (int q = 0; q < 8; ++q) {
            int rr = w + 16 * q;
            float v = x[(((size_t)b * Nn + (J + rr)) * Nn + i) * Cc + lane];
            __nv_bfloat16 h = __float2bfloat16_rn(v);
            __nv_bfloat16 l = __float2bfloat16_rn(v - __bfloat162float(h));
            A0[rr * RSA + 32 + lane] = h;
            A0[rr * RSA + 96 + lane] = l;
        }
    }
    __syncthreads();

    const int arow0 = mrow * 16 + g;
    const uint32_t aOffWarp = (uint32_t)(((mrow * 16 + (lane & 15)) * RSA + (lane >> 4) * 8) * 2);
    const uint32_t bBase = smem_u32(Wsm)
        + (uint32_t)(((ngrp * 128 + ((lane >> 3) & 1) * 8 + (lane & 7)) * RSB
                      + (lane >> 4) * 8) * 2);
    const int m0 = ngrp * 2, m1 = m0 + 1;

    int parity = 0;
    for (int L = blockIdx.x; L < NITEMS; L += GRID_P) {
        const int i = L & 255, b = (L >> 8) & 3, J = (L >> 10) * 128;
        const int Ln = L + GRID_P;
        const bool has_next = (Ln < NITEMS);

        // ---- prefetch next item's x into registers ----
        float4 pf0, pf1; float pfj[8];
        int ni = 0, nb = 0, nJ = 0;
        if (has_next) {
            ni = Ln & 255; nb = (Ln >> 8) & 3; nJ = (Ln >> 10) * 128;
            const float4* nx4 = (const float4*)(x + (((size_t)nb * Nn + ni) * Nn + nJ) * Cc);
            pf0 = nx4[tid];
            pf1 = nx4[tid + 512];
            #pragma unroll
            for (int q = 0; q < 8; ++q) {
                int rr = w + 16 * q;
                pfj[q] = x[(((size_t)nb * Nn + (nJ + rr)) * Nn + ni) * Cc + lane];
            }
        }

        // ---- s values for this thread's rows/m's ----
        float ei0 = g_e[((size_t)b * Nn + i) * 4 + m0];
        float ei1 = g_e[((size_t)b * Nn + i) * 4 + m1];
        float ej00 = g_e[((size_t)b * Nn + J + arow0) * 4 + m0];
        float ej01 = g_e[((size_t)b * Nn + J + arow0) * 4 + m1];
        float ej10 = g_e[((size_t)b * Nn + J + arow0 + 8) * 4 + m0];
        float ej11 = g_e[((size_t)b * Nn + J + arow0 + 8) * 4 + m1];
        float s00 = ei0 * ej00, s01 = ei1 * ej01;
        float s10 = ei0 * ej10, s11 = ei1 * ej11;

        __nv_bfloat16* Acur = parity ? A1 : A0;
        __nv_bfloat16* Anxt = parity ? A0 : A1;
        const uint32_t aBase = smem_u32(Acur) + aOffWarp;

        // ---- MMA mainloop ----
        float acc[16][4];
        #pragma unroll
        for (int u = 0; u < 16; ++u) {
            acc[u][0] = 0.f; acc[u][1] = 0.f; acc[u][2] = 0.f; acc[u][3] = 0.f;
        }
        #pragma unroll
        for (int kki = 0; kki < 4; ++kki) {
            const int kk = kki * 16;
            uint32_t ah0, ah1, ah2, ah3, al0, al1, al2, al3;
            ldsm4(ah0, ah1, ah2, ah3, aBase + kk * 2);
            ldsm4(al0, al1, al2, al3, aBase + (kk + 64) * 2);
            #pragma unroll
            for (int p = 0; p < 8; ++p) {
                uint32_t bh0, bh1, bh2, bh3, bl0, bl1, bl2, bl3;
                const uint32_t bb = bBase + (uint32_t)((p * 16 * RSB + kk) * 2);
                ldsm4(bh0, bh1, bh2, bh3, bb);
                ldsm4(bl0, bl1, bl2, bl3, bb + 128);
                float* c0 = acc[2 * p];
                float* c1 = acc[2 * p + 1];
                mma_bf16(c0, ah0, ah1, ah2, ah3, bh0, bh2);
                mma_bf16(c1, ah0, ah1, ah2, ah3, bh1, bh3);
                mma_bf16(c0, al0, al1, al2, al3, bh0, bh2);
                mma_bf16(c1, al0, al1, al2, al3, bh1, bh3);
                mma_bf16(c0, ah0, ah1, ah2, ah3, bl0, bl2);
                mma_bf16(c1, ah0, ah1, ah2, ah3, bl1, bl3);
            }
        }

        // ---- store next item's A tile (convert hi/lo) ----
        if (has_next) {
            sts_split_xij(Anxt, r_ij, c_ij, pf0);
            sts_split_xij(Anxt, r_ij2, c_ij2, pf1);
            #pragma unroll
            for (int q = 0; q < 8; ++q) {
                int rr = w + 16 * q;
                float v = pfj[q];
                __nv_bfloat16 h = __float2bfloat16_rn(v);
                __nv_bfloat16 l = __float2bfloat16_rn(v - __bfloat162float(h));
                Anxt[rr * RSA + 32 + lane] = h;
                Anxt[rr * RSA + 96 + lane] = l;
            }
        }

        // ---- epilogue phase 1: ngrp1 writes s-weighted partials to R ----
        float* Rb = Rbuf[parity];
        if (ngrp == 1) {
            int r0 = arow0, r1 = arow0 + 8;
            #pragma unroll
            for (int oct = 0; oct < 8; ++oct) {
                int o = oct * 8 + tig * 2;
                float2 v0, v1;
                v0.x = s00 * acc[oct][0] + s01 * acc[oct + 8][0];
                v0.y = s00 * acc[oct][1] + s01 * acc[oct + 8][1];
                v1.x = s10 * acc[oct][2] + s11 * acc[oct + 8][2];
                v1.y = s10 * acc[oct][3] + s11 * acc[oct + 8][3];
                *(float2*)&Rb[r0 * RSR + o] = v0;
                *(float2*)&Rb[r1 * RSR + o] = v1;
            }
        }
        __syncthreads();

        // ---- epilogue phase 2: ngrp0 merges R + own + Add, writes out ----
        if (ngrp == 0) {
            int r0 = arow0, r1 = arow0 + 8;
            const float* add0 = &g_Add[((size_t)b * Nn + J + r0) * 64];
            const float* add1 = &g_Add[((size_t)b * Nn + J + r1) * 64];
            float* o0 = &out[(((size_t)b * Nn + i) * Nn + (J + r0)) * 64];
            float* o1 = &out[(((size_t)b * Nn + i) * Nn + (J + r1)) * 64];
            #pragma unroll
            for (int oct = 0; oct < 8; ++oct) {
                int o = oct * 8 + tig * 2;
                float2 a0v = *(const float2*)&add0[o];
                float2 a1v = *(const float2*)&add1[o];
                float2 r0v = *(const float2*)&Rb[r0 * RSR + o];
                float2 r1v = *(const float2*)&Rb[r1 * RSR + o];
                float2 v0, v1;
                v0.x = s00 * acc[oct][0] + s01 * acc[oct + 8][0] + r0v.x + a0v.x;
                v0.y = s00 * acc[oct][1] + s01 * acc[oct + 8][1] + r0v.y + a0v.y;
                v1.x = s10 * acc[oct][2] + s11 * acc[oct + 8][2] + r1v.x + a1v.x;
                v1.y = s10 * acc[oct][3] + s11 * acc[oct + 8][3] + r1v.y + a1v.y;
                *(float2*)&o0[o] = v0;
                *(float2*)&o1[o] = v1;
            }
        }
        parity ^= 1;
    }
}

// ---------------- launcher ----------------
extern "C" void kernel_launch(void* const* d_in, const int* in_sizes, int n_in,
                              void* d_out, int out_size) {
    const float* x     = (const float*)d_in[0];
    const float* w1_nb = (const float*)d_in[1];
    const float* b1_nb = (const float*)d_in[2];
    const float* w0_nb = (const float*)d_in[3];
    const float* b0_nb = (const float*)d_in[4];
    const float* w2d   = (const float*)d_in[5];
    const float* b2d   = (const float*)d_in[6];
    const float* w1d   = (const float*)d_in[7];
    const float* b1d   = (const float*)d_in[8];
    const float* w0d   = (const float*)d_in[9];
    const float* b0d   = (const float*)d_in[10];
    float* out = (float*)d_out;

    k_wprep<<<32, 256>>>(w2d);
    k_contract1<<<Bb * Nn, 256>>>(x);
    k_neighbs<<<Bb, 256>>>(w1_nb, b1_nb, w0_nb, b0_nb);
    k_weighted<<<Bb * Nn, 256>>>(x);
    k_c0<<<Bb, 1024>>>(w0d, b0d, b2d);
    k_add<<<Bb * Nn, 128>>>(w1d, b1d);

    cudaFuncSetAttribute(k_main_p, cudaFuncAttributeMaxDynamicSharedMemorySize, SM_BYTES);
    k_main_p<<<GRID_P, 512, SM_BYTES>>>(x, out);
}